// round 9
// baseline (speedup 1.0000x reference)
#include <cuda_runtime.h>
#include <cuda_bf16.h>
#include <math.h>

#define HW 65536
#define CMID 64

// ---- scratch (device globals; allocation is forbidden) ----
__device__ float g_y[4 * CMID * HW];      // after input conv1x1  (64 MiB)
__device__ float g_edge[4 * CMID * HW];   // raw edge map         (64 MiB)
__device__ float g_sums[4 * CMID];        // per-(b,c) raw-edge sums
__device__ unsigned int g_maxbits;        // global max (float bits, all >= 0)
// W fragments in mma B-layout: [s][ks][nt][lane] -> uint4(bh0,bh1,bl0,bl1)
__device__ uint4 g_wfin[8 * 2 * 8 * 32];          // conv_in  (64 KB)
__device__ uint4 g_wfout[4 * 2 * 2 * 8 * 32];     // conv_out, per batch (64 KB)

// ---- dynamic smem layout (bytes) ----
#define XSP 132                           // fp32 staging pitch (floats)
#define XS0_OFF 0                         // 32 x 132 x 4 = 16896
#define XS1_OFF 16896
#define XPITCH 136                        // bf16 X pitch
#define XH_OFF 33792                      // 32 x 136 x 2 = 8704
#define XL_OFF 42496
#define SMEM_SZ 51200
// epilogue reuses [0, 33792) as fp32 [64][132] transpose buffer

// ============================ PTX helpers ==================================
__device__ __forceinline__ unsigned smem_u32(const void* p) {
    unsigned a;
    asm("{ .reg .u64 t; cvta.to.shared.u64 t, %1; cvt.u32.u64 %0, t; }" : "=r"(a) : "l"(p));
    return a;
}
__device__ __forceinline__ void cpa16(unsigned d, const void* s) {
    asm volatile("cp.async.cg.shared.global [%0], [%1], 16;" :: "r"(d), "l"(s));
}
#define CPCOMMIT() asm volatile("cp.async.commit_group;" ::: "memory")
template <int N> __device__ __forceinline__ void cpwait() {
    asm volatile("cp.async.wait_group %0;" :: "n"(N) : "memory");
}
__device__ __forceinline__ void ldsm4t(unsigned& r0, unsigned& r1, unsigned& r2,
                                       unsigned& r3, unsigned a) {
    asm volatile("ldmatrix.sync.aligned.m8n8.x4.trans.shared.b16 {%0,%1,%2,%3}, [%4];"
                 : "=r"(r0), "=r"(r1), "=r"(r2), "=r"(r3) : "r"(a));
}
__device__ __forceinline__ void mma16816(float* d, const unsigned* a,
                                         unsigned b0, unsigned b1) {
    asm volatile("mma.sync.aligned.m16n8k16.row.col.f32.bf16.bf16.f32 "
                 "{%0,%1,%2,%3},{%4,%5,%6,%7},{%8,%9},{%0,%1,%2,%3};"
                 : "+f"(d[0]), "+f"(d[1]), "+f"(d[2]), "+f"(d[3])
                 : "r"(a[0]), "r"(a[1]), "r"(a[2]), "r"(a[3]), "r"(b0), "r"(b1));
}
__device__ __forceinline__ unsigned pk(float a, float b) {
    __nv_bfloat162 t(__float2bfloat16(a), __float2bfloat16(b));
    return *(unsigned*)&t;
}

// ===========================================================================
// Prep: split w_in into mma-fragment-ordered bf16 hi/lo; zero reduction state.
// idx -> lane(5) | nt(3) | ks(1) | s(3)
__global__ void k_prep_in(const float* __restrict__ w_in) {
    int idx = blockIdx.x * 256 + threadIdx.x;      // 0..4095
    if (blockIdx.x == 0) {
        g_sums[threadIdx.x] = 0.f;
        if (threadIdx.x == 0) g_maxbits = 0u;
    }
    int lane = idx & 31, nt = (idx >> 5) & 7, ks = (idx >> 8) & 1, s = idx >> 9;
    int o = nt * 8 + (lane >> 2);
    int c = s * 32 + ks * 16 + (lane & 3) * 2;
    float v0 = w_in[o * 256 + c],     v1 = w_in[o * 256 + c + 1];
    float v2 = w_in[o * 256 + c + 8], v3 = w_in[o * 256 + c + 9];
    float h0 = __bfloat162float(__float2bfloat16(v0));
    float h1 = __bfloat162float(__float2bfloat16(v1));
    float h2 = __bfloat162float(__float2bfloat16(v2));
    float h3 = __bfloat162float(__float2bfloat16(v3));
    g_wfin[idx] = make_uint4(pk(h0, h1), pk(h2, h3),
                             pk(v0 - h0, v1 - h1), pk(v2 - h2, v3 - h3));
}

// Prep: SE head + fold into w_out, emit fragment-ordered hi/lo per batch.
// idx -> lane(5) | nt(3) | ks(1) | s(1) | b(2)
__global__ void k_prep_out(const float* __restrict__ w_fc1, const float* __restrict__ b_fc1,
                           const float* __restrict__ w_fc2, const float* __restrict__ b_fc2,
                           const float* __restrict__ w_out) {
    int idx = blockIdx.x * 256 + threadIdx.x;      // 0..4095
    int lane = idx & 31, nt = (idx >> 5) & 7, ks = (idx >> 8) & 1;
    int s = (idx >> 9) & 1, b = idx >> 10;
    int o = nt * 8 + (lane >> 2);
    int c = s * 32 + ks * 16 + (lane & 3) * 2;

    float inv = 1.f / (__uint_as_float(g_maxbits) + 1e-8f);
    float hh[4];
#pragma unroll
    for (int j = 0; j < 4; ++j) {
        float acc = b_fc1[j];
        for (int cc = 0; cc < 64; ++cc)
            acc = fmaf(w_fc1[j * 64 + cc], g_sums[b * 64 + cc] * (1.f / 65536.f) * inv, acc);
        hh[j] = fmaxf(acc, 0.f);
    }
    float wv[4];
#pragma unroll
    for (int i = 0; i < 4; ++i) {
        int cc = c + (i >> 1) * 8 + (i & 1);
        float sc = b_fc2[cc];
#pragma unroll
        for (int j = 0; j < 4; ++j) sc = fmaf(w_fc2[cc * 4 + j], hh[j], sc);
        float fmul = inv / (1.f + expf(-sc));
        wv[i] = w_out[o * 64 + cc] * fmul;
    }
    float h0 = __bfloat162float(__float2bfloat16(wv[0]));
    float h1 = __bfloat162float(__float2bfloat16(wv[1]));
    float h2 = __bfloat162float(__float2bfloat16(wv[2]));
    float h3 = __bfloat162float(__float2bfloat16(wv[3]));
    g_wfout[idx] = make_uint4(pk(h0, h1), pk(h2, h3),
                              pk(wv[0] - h0, wv[1] - h1), pk(wv[2] - h2, wv[3] - h3));
}

// ===========================================================================
// conv1x1 via mma.sync bf16 3-term split + cp.async pipelined X staging +
// gmem fragment-ordered W (no W smem). 128 threads / 4 warps, m32 x n64 each.
template <int CH>
__global__ void __launch_bounds__(128, 4) k_conv(
    const float* __restrict__ src, int cin,
    const uint4* __restrict__ wfrag, int wfstride,
    const float* __restrict__ bias, float* __restrict__ dst) {
    extern __shared__ char sm[];
    unsigned smb = smem_u32(sm);
    int tid = threadIdx.x;
    int w   = tid >> 5, lane = tid & 31;

    int t    = blockIdx.x;
    int b    = t >> 9;           // 512 tiles per batch
    int pix0 = (t & 511) << 7;   // 128 pixels per tile

    const float* srcb = src + (size_t)b * cin * HW + pix0;
    const uint4* wfp  = wfrag + b * wfstride;

    auto issue_x = [&](int cs, int buf) {
        const float* base = srcb + (size_t)(cs * 32) * HW;
        unsigned db = smb + (buf ? XS1_OFF : XS0_OFF);
#pragma unroll
        for (int k = 0; k < 8; ++k) {
            int seg = tid + k * 128;               // 0..1023
            int row = seg >> 5, off = (seg & 31) * 4;
            cpa16(db + (unsigned)(row * XSP + off) * 4, base + (size_t)row * HW + off);
        }
    };

    issue_x(0, 0); CPCOMMIT();
    if (CH > 1) { issue_x(1, 1); CPCOMMIT(); }

    float acc[2][8][4];
#pragma unroll
    for (int mt = 0; mt < 2; ++mt)
#pragma unroll
        for (int nt = 0; nt < 8; ++nt)
#pragma unroll
            for (int i = 0; i < 4; ++i) acc[mt][nt][i] = 0.f;

    int arow  = (lane & 7) + ((lane >> 4) << 3);
    int acol0 = (w << 5) + (((lane >> 3) & 1) << 3);

    for (int s = 0; s < CH; ++s) {
        if (s + 1 < CH) cpwait<1>(); else cpwait<0>();
        __syncthreads();

        // ---- X convert: XS[s&1] fp32 [c][pix] -> XH/XL bf16
        {
            const char* xs = sm + ((s & 1) ? XS1_OFF : XS0_OFF);
            int cw = w * 32;
            unsigned xoff = (unsigned)((lane * XPITCH + cw) * 2);
#pragma unroll
            for (int i = 0; i < 4; ++i) {
                float4 v0 = *(const float4*)(xs + (lane * XSP + cw + i * 8) * 4);
                float4 v1 = *(const float4*)(xs + (lane * XSP + cw + i * 8 + 4) * 4);
                float h0 = __bfloat162float(__float2bfloat16(v0.x));
                float h1 = __bfloat162float(__float2bfloat16(v0.y));
                float h2 = __bfloat162float(__float2bfloat16(v0.z));
                float h3 = __bfloat162float(__float2bfloat16(v0.w));
                float h4 = __bfloat162float(__float2bfloat16(v1.x));
                float h5 = __bfloat162float(__float2bfloat16(v1.y));
                float h6 = __bfloat162float(__float2bfloat16(v1.z));
                float h7 = __bfloat162float(__float2bfloat16(v1.w));
                *(uint4*)(sm + XH_OFF + xoff + i * 16) =
                    make_uint4(pk(h0, h1), pk(h2, h3), pk(h4, h5), pk(h6, h7));
                *(uint4*)(sm + XL_OFF + xoff + i * 16) =
                    make_uint4(pk(v0.x - h0, v0.y - h1), pk(v0.z - h2, v0.w - h3),
                               pk(v1.x - h4, v1.y - h5), pk(v1.z - h6, v1.w - h7));
            }
        }
        __syncthreads();

        if (s + 2 < CH) { issue_x(s + 2, s & 1); CPCOMMIT(); }

        // ---- MMA: 2 k-steps of 16; W fragments from gmem (L1/L2-hot)
#pragma unroll
        for (int ks = 0; ks < 2; ++ks) {
            unsigned ah[2][4], al[2][4];
#pragma unroll
            for (int mt = 0; mt < 2; ++mt) {
                unsigned aoff = (unsigned)(((ks * 16 + arow) * XPITCH + acol0 + mt * 16) * 2);
                ldsm4t(ah[mt][0], ah[mt][1], ah[mt][2], ah[mt][3], smb + XH_OFF + aoff);
                ldsm4t(al[mt][0], al[mt][1], al[mt][2], al[mt][3], smb + XL_OFF + aoff);
            }
            const uint4* wk = wfp + ((s * 2 + ks) * 8) * 32 + lane;
#pragma unroll
            for (int nt = 0; nt < 8; ++nt) {
                uint4 f = wk[nt * 32];
#pragma unroll
                for (int mt = 0; mt < 2; ++mt) {
                    mma16816(acc[mt][nt], ah[mt], f.x, f.y);
                    mma16816(acc[mt][nt], al[mt], f.x, f.y);
                    mma16816(acc[mt][nt], ah[mt], f.z, f.w);
                }
            }
        }
    }

    // ---- epilogue: bias add, transpose through smem, coalesced 512B rows
    __syncthreads();
    float* eb = (float*)sm;                        // fp32 [64][XSP]
    int g  = lane >> 2;
    int t2 = (lane & 3) * 2;
#pragma unroll
    for (int mt = 0; mt < 2; ++mt) {
        int px = w * 32 + mt * 16;
#pragma unroll
        for (int nt = 0; nt < 8; ++nt) {
            int o0 = nt * 8 + t2;
            float b0 = __ldg(bias + o0), b1 = __ldg(bias + o0 + 1);
            eb[o0 * XSP + px + g]           = acc[mt][nt][0] + b0;
            eb[(o0 + 1) * XSP + px + g]     = acc[mt][nt][1] + b1;
            eb[o0 * XSP + px + g + 8]       = acc[mt][nt][2] + b0;
            eb[(o0 + 1) * XSP + px + g + 8] = acc[mt][nt][3] + b1;
        }
    }
    __syncthreads();
    float* dp = dst + (size_t)b * CMID * HW + pix0;
#pragma unroll
    for (int r = 0; r < 16; ++r) {
        int o = r * 4 + w;
        float4 v = *(const float4*)(eb + o * XSP + lane * 4);
        *(float4*)(dp + (size_t)o * HW + lane * 4) = v;
    }
}

// ---------------------------------------------------------------------------
// Fused depthwise stage (identical to the 241us run)
__global__ void __launch_bounds__(256) k_edge() {
    __shared__ float ys[38][40];
    __shared__ float ts[34][40];
    __shared__ float ss[34][36];
    __shared__ float rs[8], rm[8];

    int tid   = threadIdx.x;
    int plane = blockIdx.y;
    int tile  = blockIdx.x;
    int ty0 = (tile >> 3) * 32;
    int tx0 = (tile & 7) * 32;
    const float* yp = g_y + (size_t)plane * HW;

    for (int i = tid; i < 38 * 38; i += 256) {
        int r = i / 38, c = i - r * 38;
        int gy = ty0 - 3 + r, gx = tx0 - 3 + c;
        float v = 0.f;
        if ((unsigned)gy < 256u && (unsigned)gx < 256u) v = yp[gy * 256 + gx];
        ys[r][c] = v;
    }
    __syncthreads();

    const float g1 = expf(-0.125f), g2 = expf(-0.5f);

    if (tid < 228) {
        int c = tid % 38, rg = tid / 38;
        int k0 = rg * 6;
        float y0 = ys[k0][c],     y1 = ys[k0 + 1][c], y2 = ys[k0 + 2][c];
        float y3 = ys[k0 + 3][c], y4 = ys[k0 + 4][c];
#pragma unroll
        for (int j = 0; j < 6; ++j) {
            int k = k0 + j;
            if (k < 34) {
                ts[k][c] = g2 * (y0 + y4) + g1 * (y1 + y3) + y2;
                y0 = y1; y1 = y2; y2 = y3; y3 = y4;
                if (k + 5 < 38) y4 = ys[k + 5][c];
            }
        }
    }
    __syncthreads();

    if (tid < 238) {
        int r = tid / 7, cg = tid % 7;
        int j0 = cg * 5;
        float t0 = ts[r][j0],     t1 = ts[r][j0 + 1], t2 = ts[r][j0 + 2];
        float t3 = ts[r][j0 + 3], t4 = ts[r][j0 + 4];
        int gy = ty0 - 1 + r;
#pragma unroll
        for (int u = 0; u < 5; ++u) {
            int j = j0 + u;
            if (j < 34) {
                float v = g2 * (t0 + t4) + g1 * (t1 + t3) + t2;
                int gx = tx0 - 1 + j;
                if ((unsigned)gy >= 256u || (unsigned)gx >= 256u) v = 0.f;
                ss[r][j] = v;
                t0 = t1; t1 = t2; t2 = t3; t3 = t4;
                if (j + 5 < 38) t4 = ts[r][j + 5];
            }
        }
    }
    __syncthreads();

    int tx = tid & 15, ty = tid >> 4;
    int r0 = 2 * ty, c0 = 2 * tx;
    float sv[4][4];
#pragma unroll
    for (int a2 = 0; a2 < 4; ++a2)
#pragma unroll
        for (int b2 = 0; b2 < 4; ++b2) sv[a2][b2] = ss[r0 + a2][c0 + b2];

    float lsum = 0.f, lmax = 0.f;
    float* ep = g_edge + (size_t)plane * HW;
#pragma unroll
    for (int dr = 0; dr < 2; ++dr)
#pragma unroll
        for (int dc = 0; dc < 2; ++dc) {
            float a  = sv[dr][dc],     bb = sv[dr][dc + 1],     cv = sv[dr][dc + 2];
            float d  = sv[dr + 1][dc], e  = sv[dr + 1][dc + 1], f  = sv[dr + 1][dc + 2];
            float g  = sv[dr + 2][dc], h  = sv[dr + 2][dc + 1], ii = sv[dr + 2][dc + 2];
            float g0  = 3.f * (a - cv) + 10.f * (d - f) + 3.f * (g - ii);
            float g90 = 3.f * (a - g)  + 10.f * (bb - h) + 3.f * (cv - ii);
            float lap = 4.f * e - bb - d - f - h;
            float edge = fmaxf(fabsf(g0), fabsf(g90)) + 0.1f * fabsf(lap);
            ep[(ty0 + r0 + dr) * 256 + tx0 + c0 + dc] = edge;
            lsum += edge;
            lmax = fmaxf(lmax, edge);
        }

#pragma unroll
    for (int off = 16; off; off >>= 1) {
        lsum += __shfl_down_sync(0xffffffffu, lsum, off);
        lmax = fmaxf(lmax, __shfl_down_sync(0xffffffffu, lmax, off));
    }
    int wid = tid >> 5, lane = tid & 31;
    if (lane == 0) { rs[wid] = lsum; rm[wid] = lmax; }
    __syncthreads();
    if (tid == 0) {
        float s = 0.f, m = 0.f;
#pragma unroll
        for (int w2 = 0; w2 < 8; ++w2) { s += rs[w2]; m = fmaxf(m, rm[w2]); }
        atomicAdd(&g_sums[plane], s);
        atomicMax(&g_maxbits, __float_as_uint(m));
    }
}

// ---------------------------------------------------------------------------
extern "C" void kernel_launch(void* const* d_in, const int* in_sizes, int n_in,
                              void* d_out, int out_size) {
    const float* x     = (const float*)d_in[0];
    const float* w_in  = (const float*)d_in[1];
    const float* b_in  = (const float*)d_in[2];
    const float* w_fc1 = (const float*)d_in[3];
    const float* b_fc1 = (const float*)d_in[4];
    const float* w_fc2 = (const float*)d_in[5];
    const float* b_fc2 = (const float*)d_in[6];
    const float* w_out = (const float*)d_in[7];
    const float* b_out = (const float*)d_in[8];
    float* out = (float*)d_out;

    cudaFuncSetAttribute(k_conv<8>, cudaFuncAttributeMaxDynamicSharedMemorySize, SMEM_SZ);
    cudaFuncSetAttribute(k_conv<2>, cudaFuncAttributeMaxDynamicSharedMemorySize, SMEM_SZ);

    float* gy = nullptr;
    float* gedge = nullptr;
    uint4 *wfin, *wfout;
    cudaGetSymbolAddress((void**)&gy, g_y);
    cudaGetSymbolAddress((void**)&gedge, g_edge);
    cudaGetSymbolAddress((void**)&wfin, g_wfin);
    cudaGetSymbolAddress((void**)&wfout, g_wfout);

    k_prep_in<<<16, 256>>>(w_in);
    k_conv<8><<<2048, 128, SMEM_SZ>>>(x, 256, wfin, 0, b_in, gy);
    k_edge<<<dim3(64, 256), 256>>>();
    k_prep_out<<<16, 256>>>(w_fc1, b_fc1, w_fc2, b_fc2, w_out);
    k_conv<2><<<2048, 128, SMEM_SZ>>>(gedge, 64, wfout, 1024, b_out, out);
}

// round 11
// speedup vs baseline: 1.3388x; 1.3388x over previous
#include <cuda_runtime.h>
#include <cuda_bf16.h>
#include <math.h>

#define HW 65536
#define CMID 64

// ---- scratch (device globals; allocation is forbidden) ----
__device__ float g_y[4 * CMID * HW];      // after input conv1x1  (64 MiB)
__device__ float g_edge[4 * CMID * HW];   // raw edge map         (64 MiB)
__device__ float g_sums[4 * CMID];        // per-(b,c) raw-edge sums
__device__ unsigned int g_maxbits;        // global max (float bits, all >= 0)

// ---- dynamic smem layout (bytes) ----
#define XSP 132                           // fp32 staging pitch (floats)
#define XS0_OFF 0                         // 32 x 132 x 4 = 16896
#define XS1_OFF 16896
#define XPITCH 136                        // bf16 X pitch
#define XH_OFF 33792                      // 32 x 136 x 2 = 8704
#define XL_OFF 42496
#define WPITCH 40                         // bf16 W pitch (32 + 8 pad)
#define WH_OFF 51200                      // 64 x 40 x 2 = 5120
#define WL_OFF 56320
#define FM_OFF 61440
#define PL_OFF 61696
#define HH_OFF 61952
#define SMEM_SZ 62208

// ============================ PTX helpers ==================================
__device__ __forceinline__ unsigned smem_u32(const void* p) {
    unsigned a;
    asm("{ .reg .u64 t; cvta.to.shared.u64 t, %1; cvt.u32.u64 %0, t; }" : "=r"(a) : "l"(p));
    return a;
}
__device__ __forceinline__ void cpa16(unsigned d, const void* s) {
    asm volatile("cp.async.cg.shared.global [%0], [%1], 16;" :: "r"(d), "l"(s));
}
#define CPCOMMIT() asm volatile("cp.async.commit_group;" ::: "memory")
template <int N> __device__ __forceinline__ void cpwait() {
    asm volatile("cp.async.wait_group %0;" :: "n"(N) : "memory");
}
__device__ __forceinline__ void ldsm4t(unsigned& r0, unsigned& r1, unsigned& r2,
                                       unsigned& r3, unsigned a) {
    asm volatile("ldmatrix.sync.aligned.m8n8.x4.trans.shared.b16 {%0,%1,%2,%3}, [%4];"
                 : "=r"(r0), "=r"(r1), "=r"(r2), "=r"(r3) : "r"(a));
}
__device__ __forceinline__ void ldsm4(unsigned& r0, unsigned& r1, unsigned& r2,
                                      unsigned& r3, unsigned a) {
    asm volatile("ldmatrix.sync.aligned.m8n8.x4.shared.b16 {%0,%1,%2,%3}, [%4];"
                 : "=r"(r0), "=r"(r1), "=r"(r2), "=r"(r3) : "r"(a));
}
__device__ __forceinline__ void mma16816(float* d, const unsigned* a,
                                         unsigned b0, unsigned b1) {
    asm volatile("mma.sync.aligned.m16n8k16.row.col.f32.bf16.bf16.f32 "
                 "{%0,%1,%2,%3},{%4,%5,%6,%7},{%8,%9},{%0,%1,%2,%3};"
                 : "+f"(d[0]), "+f"(d[1]), "+f"(d[2]), "+f"(d[3])
                 : "r"(a[0]), "r"(a[1]), "r"(a[2]), "r"(a[3]), "r"(b0), "r"(b1));
}
__device__ __forceinline__ unsigned pk(float a, float b) {
    __nv_bfloat162 t(__float2bfloat16(a), __float2bfloat16(b));
    return *(unsigned*)&t;
}

// ===========================================================================
// conv1x1 via mma.sync bf16 3-term split + cp.async pipelined staging.
// (identical to the 241.3us run)
template <int CH, int FOLD>
__global__ void __launch_bounds__(128, 3) k_conv(
    const float* __restrict__ src, int cin,
    const float* __restrict__ wsrc, int wrow,
    const float* __restrict__ bias, float* __restrict__ dst,
    const float* __restrict__ w_fc1, const float* __restrict__ b_fc1,
    const float* __restrict__ w_fc2, const float* __restrict__ b_fc2) {
    extern __shared__ char sm[];
    unsigned smb = smem_u32(sm);
    int tid = threadIdx.x;
    int w   = tid >> 5, lane = tid & 31;

    int t    = blockIdx.x;
    int b    = t >> 9;           // 512 tiles per batch
    int pix0 = (t & 511) << 7;   // 128 pixels per tile

    if (!FOLD && blockIdx.x == 0) {   // init for this replay's edge stage
        g_sums[tid] = 0.f;
        g_sums[tid + 128] = 0.f;
        if (tid == 0) g_maxbits = 0u;
    }

    if (FOLD) {   // SE head: per-channel fmul = sigmoid(fc2(relu(fc1(pooled))))*inv
        float* pooled = (float*)(sm + PL_OFF);
        float* hh     = (float*)(sm + HH_OFF);
        float* fm     = (float*)(sm + FM_OFF);
        float inv = 1.f / (__uint_as_float(g_maxbits) + 1e-8f);
        if (tid < 64) pooled[tid] = g_sums[b * 64 + tid] * (1.f / 65536.f) * inv;
        __syncthreads();
        if (tid < 4) {
            float s = b_fc1[tid];
            for (int cc = 0; cc < 64; ++cc) s = fmaf(w_fc1[tid * 64 + cc], pooled[cc], s);
            hh[tid] = fmaxf(s, 0.f);
        }
        __syncthreads();
        if (tid < 64) {
            float sc = b_fc2[tid];
#pragma unroll
            for (int j = 0; j < 4; ++j) sc = fmaf(w_fc2[tid * 4 + j], hh[j], sc);
            fm[tid] = inv / (1.f + expf(-sc));
        }
        __syncthreads();
    }

    const float* srcb = src + (size_t)b * cin * HW + pix0;

    auto issue_x = [&](int cs, int buf) {
        const float* base = srcb + (size_t)(cs * 32) * HW;
        unsigned db = smb + (buf ? XS1_OFF : XS0_OFF);
#pragma unroll
        for (int k = 0; k < 8; ++k) {
            int seg = tid + k * 128;               // 0..1023
            int row = seg >> 5, off = (seg & 31) * 4;
            cpa16(db + (unsigned)(row * XSP + off) * 4, base + (size_t)row * HW + off);
        }
    };

    issue_x(0, 0); CPCOMMIT();
    if (CH > 1) { issue_x(1, 1); CPCOMMIT(); }

    float acc[2][8][4];
#pragma unroll
    for (int mt = 0; mt < 2; ++mt)
#pragma unroll
        for (int nt = 0; nt < 8; ++nt)
#pragma unroll
            for (int i = 0; i < 4; ++i) acc[mt][nt][i] = 0.f;

    int arow  = (lane & 7) + ((lane >> 4) << 3);
    int acol0 = (w << 5) + (((lane >> 3) & 1) << 3);
    int brow2 = ((lane >> 4) << 3) + (lane & 7);
    int bcol  = ((lane >> 3) & 1) << 3;

    for (int s = 0; s < CH; ++s) {
        if (s + 1 < CH) cpwait<1>(); else cpwait<0>();
        __syncthreads();

        // ---- W LDG first (L2-hot; latency hidden behind X convert below)
        int wo = tid >> 1, wc = (tid & 1) * 16;
        const float* wp = wsrc + wo * wrow + s * 32 + wc;
        float4 wa = *(const float4*)wp;
        float4 wb4 = *(const float4*)(wp + 4);
        float4 wcv = *(const float4*)(wp + 8);
        float4 wd = *(const float4*)(wp + 12);

        // ---- X convert: XS[s&1] fp32 [c][pix] -> XH/XL bf16
        {
            const char* xs = sm + ((s & 1) ? XS1_OFF : XS0_OFF);
            int cw = w * 32;
            unsigned hibuf[16], lobuf[16];
#pragma unroll
            for (int i = 0; i < 8; ++i) {
                float4 v = *(const float4*)(xs + (lane * XSP + cw + i * 4) * 4);
                float h0 = __bfloat162float(__float2bfloat16(v.x));
                float h1 = __bfloat162float(__float2bfloat16(v.y));
                float h2 = __bfloat162float(__float2bfloat16(v.z));
                float h3 = __bfloat162float(__float2bfloat16(v.w));
                hibuf[i * 2]     = pk(h0, h1);
                hibuf[i * 2 + 1] = pk(h2, h3);
                lobuf[i * 2]     = pk(v.x - h0, v.y - h1);
                lobuf[i * 2 + 1] = pk(v.z - h2, v.w - h3);
            }
            unsigned xoff = (unsigned)((lane * XPITCH + cw) * 2);
#pragma unroll
            for (int j = 0; j < 4; ++j) {
                *(uint4*)(sm + XH_OFF + xoff + j * 16) =
                    make_uint4(hibuf[j * 4], hibuf[j * 4 + 1], hibuf[j * 4 + 2], hibuf[j * 4 + 3]);
                *(uint4*)(sm + XL_OFF + xoff + j * 16) =
                    make_uint4(lobuf[j * 4], lobuf[j * 4 + 1], lobuf[j * 4 + 2], lobuf[j * 4 + 3]);
            }
        }

        // ---- W split + STS (FOLD: scale by fm first)
        {
            float wv[16] = {wa.x, wa.y, wa.z, wa.w, wb4.x, wb4.y, wb4.z, wb4.w,
                            wcv.x, wcv.y, wcv.z, wcv.w, wd.x, wd.y, wd.z, wd.w};
            if (FOLD) {
                const float* fm = (const float*)(sm + FM_OFF);
#pragma unroll
                for (int i = 0; i < 16; ++i) wv[i] *= fm[s * 32 + wc + i];
            }
#pragma unroll
            for (int i = 0; i < 4; ++i) {
                float h0 = __bfloat162float(__float2bfloat16(wv[i * 4]));
                float h1 = __bfloat162float(__float2bfloat16(wv[i * 4 + 1]));
                float h2 = __bfloat162float(__float2bfloat16(wv[i * 4 + 2]));
                float h3 = __bfloat162float(__float2bfloat16(wv[i * 4 + 3]));
                unsigned p0 = pk(h0, h1), p1 = pk(h2, h3);
                unsigned q0 = pk(wv[i * 4] - h0, wv[i * 4 + 1] - h1);
                unsigned q1 = pk(wv[i * 4 + 2] - h2, wv[i * 4 + 3] - h3);
                unsigned woff = (unsigned)((wo * WPITCH + wc + i * 4) * 2);
                *(uint2*)(sm + WH_OFF + woff) = make_uint2(p0, p1);
                *(uint2*)(sm + WL_OFF + woff) = make_uint2(q0, q1);
            }
        }
        __syncthreads();

        if (s + 2 < CH) { issue_x(s + 2, s & 1); CPCOMMIT(); }

        // ---- MMA: 2 k-steps of 16
#pragma unroll
        for (int ks = 0; ks < 2; ++ks) {
            unsigned ah[2][4], al[2][4];
#pragma unroll
            for (int mt = 0; mt < 2; ++mt) {
                unsigned aoff = (unsigned)(((ks * 16 + arow) * XPITCH + acol0 + mt * 16) * 2);
                ldsm4t(ah[mt][0], ah[mt][1], ah[mt][2], ah[mt][3], smb + XH_OFF + aoff);
                ldsm4t(al[mt][0], al[mt][1], al[mt][2], al[mt][3], smb + XL_OFF + aoff);
            }
#pragma unroll
            for (int ntp = 0; ntp < 4; ++ntp) {
                unsigned bh[4], bl[4];
                unsigned boff = (unsigned)(((ntp * 16 + brow2) * WPITCH + ks * 16 + bcol) * 2);
                ldsm4(bh[0], bh[1], bh[2], bh[3], smb + WH_OFF + boff);
                ldsm4(bl[0], bl[1], bl[2], bl[3], smb + WL_OFF + boff);
#pragma unroll
                for (int mt = 0; mt < 2; ++mt) {
                    mma16816(acc[mt][ntp * 2],     ah[mt], bh[0], bh[1]);
                    mma16816(acc[mt][ntp * 2],     al[mt], bh[0], bh[1]);
                    mma16816(acc[mt][ntp * 2],     ah[mt], bl[0], bl[1]);
                    mma16816(acc[mt][ntp * 2 + 1], ah[mt], bh[2], bh[3]);
                    mma16816(acc[mt][ntp * 2 + 1], al[mt], bh[2], bh[3]);
                    mma16816(acc[mt][ntp * 2 + 1], ah[mt], bl[2], bl[3]);
                }
            }
        }
    }

    // ---- epilogue
    int g  = lane >> 2;
    int t2 = (lane & 3) * 2;
#pragma unroll
    for (int mt = 0; mt < 2; ++mt) {
        float* dp = dst + (size_t)b * CMID * HW + pix0 + w * 32 + mt * 16;
#pragma unroll
        for (int nt = 0; nt < 8; ++nt) {
            int o0 = nt * 8 + t2;
            float b0 = __ldg(bias + o0), b1 = __ldg(bias + o0 + 1);
            dp[(size_t)o0 * HW + g]           = acc[mt][nt][0] + b0;
            dp[(size_t)(o0 + 1) * HW + g]     = acc[mt][nt][1] + b1;
            dp[(size_t)o0 * HW + g + 8]       = acc[mt][nt][2] + b0;
            dp[(size_t)(o0 + 1) * HW + g + 8] = acc[mt][nt][3] + b1;
        }
    }
}

// ---------------------------------------------------------------------------
// Fused depthwise stage, full-width strip version: block = 256 cols x 16 rows
// of one plane. All gmem accesses are coalesced 1024B rows; halo is vertical
// only (warp-uniform row predicates). ss overlays ys (dataflow-safe).
__global__ void __launch_bounds__(256) k_edge() {
    __shared__ float smraw[10240];                  // 40960 B
    float (*ys)[256] = (float(*)[256])smraw;        // 22 rows: gy = r0-3 ..
    float (*ts)[256] = (float(*)[256])(smraw + 5632); // 18 rows: gy = r0-1 ..
    float (*ss)[260] = (float(*)[260])smraw;        // 18 x 258 used, overlays ys
    __shared__ float rs[8], rm[8];

    int tid   = threadIdx.x;
    int plane = blockIdx.y;                         // b*64 + c
    int r0    = blockIdx.x * 16;
    const float* yp = g_y + (size_t)plane * HW;

    const float g1 = expf(-0.125f), g2 = expf(-0.5f);

    // ---- load 22 coalesced rows (vertical halo 3+3, zero-padded)
#pragma unroll
    for (int rr = 0; rr < 22; ++rr) {
        int gy = r0 - 3 + rr;
        ys[rr][tid] = ((unsigned)gy < 256u) ? yp[gy * 256 + tid] : 0.f;
    }
    __syncthreads();

    // ---- vertical gaussian: thread per column, rolling 5-window, 18 outputs
    {
        int c = tid;
        float y0 = ys[0][c], y1 = ys[1][c], y2 = ys[2][c], y3 = ys[3][c], y4 = ys[4][c];
#pragma unroll
        for (int j = 0; j < 18; ++j) {
            ts[j][c] = g2 * (y0 + y4) + g1 * (y1 + y3) + y2;
            y0 = y1; y1 = y2; y2 = y3; y3 = y4;
            if (j + 5 < 22) y4 = ys[j + 5][c];
        }
    }
    __syncthreads();

    // ---- horizontal gaussian into ss[18][258] (gx = cc-1), boundary-zeroed
    for (int idx = tid; idx < 18 * 258; idx += 256) {
        int j = idx / 258, cc = idx - j * 258;
        int gx = cc - 1, gy = r0 - 1 + j;
        float v = 0.f;
        if ((unsigned)gy < 256u && (unsigned)gx < 256u) {
            float t0 = ((unsigned)(gx - 2) < 256u) ? ts[j][gx - 2] : 0.f;
            float t1 = ((unsigned)(gx - 1) < 256u) ? ts[j][gx - 1] : 0.f;
            float t2 = ts[j][gx];
            float t3 = ((unsigned)(gx + 1) < 256u) ? ts[j][gx + 1] : 0.f;
            float t4 = ((unsigned)(gx + 2) < 256u) ? ts[j][gx + 2] : 0.f;
            v = g2 * (t0 + t4) + g1 * (t1 + t3) + t2;
        }
        ss[j][cc] = v;
    }
    __syncthreads();

    // ---- stencil: thread per column, rolling 3x3 down 16 rows
    float lsum = 0.f, lmax = 0.f;
    {
        int c = tid;                                // ss col for gx=c is c+1
        float a0 = ss[0][c], a1 = ss[0][c + 1], a2 = ss[0][c + 2];
        float b0 = ss[1][c], b1 = ss[1][c + 1], b2 = ss[1][c + 2];
        float* ep = g_edge + (size_t)plane * HW + r0 * 256 + c;
#pragma unroll
        for (int i = 0; i < 16; ++i) {
            float c0 = ss[i + 2][c], c1 = ss[i + 2][c + 1], c2 = ss[i + 2][c + 2];
            float gx0 = 3.f * (a0 - a2) + 10.f * (b0 - b2) + 3.f * (c0 - c2);
            float gx9 = 3.f * (a0 - c0) + 10.f * (a1 - c1) + 3.f * (a2 - c2);
            float lap = 4.f * b1 - a1 - b0 - b2 - c1;
            float edge = fmaxf(fabsf(gx0), fabsf(gx9)) + 0.1f * fabsf(lap);
            ep[i * 256] = edge;
            lsum += edge;
            lmax = fmaxf(lmax, edge);
            a0 = b0; a1 = b1; a2 = b2;
            b0 = c0; b1 = c1; b2 = c2;
        }
    }

    // ---- block reduction -> atomics
#pragma unroll
    for (int off = 16; off; off >>= 1) {
        lsum += __shfl_down_sync(0xffffffffu, lsum, off);
        lmax = fmaxf(lmax, __shfl_down_sync(0xffffffffu, lmax, off));
    }
    int wid = tid >> 5, lane = tid & 31;
    if (lane == 0) { rs[wid] = lsum; rm[wid] = lmax; }
    __syncthreads();
    if (tid == 0) {
        float s = 0.f, m = 0.f;
#pragma unroll
        for (int w2 = 0; w2 < 8; ++w2) { s += rs[w2]; m = fmaxf(m, rm[w2]); }
        atomicAdd(&g_sums[plane], s);
        atomicMax(&g_maxbits, __float_as_uint(m));
    }
}

// ---------------------------------------------------------------------------
extern "C" void kernel_launch(void* const* d_in, const int* in_sizes, int n_in,
                              void* d_out, int out_size) {
    const float* x     = (const float*)d_in[0];
    const float* w_in  = (const float*)d_in[1];
    const float* b_in  = (const float*)d_in[2];
    const float* w_fc1 = (const float*)d_in[3];
    const float* b_fc1 = (const float*)d_in[4];
    const float* w_fc2 = (const float*)d_in[5];
    const float* b_fc2 = (const float*)d_in[6];
    const float* w_out = (const float*)d_in[7];
    const float* b_out = (const float*)d_in[8];
    float* out = (float*)d_out;

    cudaFuncSetAttribute(k_conv<8, 0>, cudaFuncAttributeMaxDynamicSharedMemorySize, SMEM_SZ);
    cudaFuncSetAttribute(k_conv<2, 1>, cudaFuncAttributeMaxDynamicSharedMemorySize, SMEM_SZ);

    float* gy = nullptr;
    float* gedge = nullptr;
    cudaGetSymbolAddress((void**)&gy, g_y);
    cudaGetSymbolAddress((void**)&gedge, g_edge);

    k_conv<8, 0><<<2048, 128, SMEM_SZ>>>(x, 256, w_in, 256, b_in, gy,
                                         nullptr, nullptr, nullptr, nullptr);
    k_edge<<<dim3(16, 256), 256>>>();
    k_conv<2, 1><<<2048, 128, SMEM_SZ>>>(gedge, 64, w_out, 64, b_out, out,
                                         w_fc1, b_fc1, w_fc2, b_fc2);
}

// round 12
// speedup vs baseline: 1.3533x; 1.0108x over previous
#include <cuda_runtime.h>
#include <cuda_bf16.h>
#include <math.h>

#define HW 65536
#define CMID 64

// ---- scratch (device globals; allocation is forbidden) ----
__device__ float g_y[4 * CMID * HW];            // after input conv1x1 (64 MiB)
__device__ __nv_bfloat16 g_eh[4 * CMID * HW];   // edge bf16 hi (32 MiB)
__device__ __nv_bfloat16 g_el[4 * CMID * HW];   // edge bf16 lo (32 MiB)
__device__ float g_sums[4 * CMID];              // per-(b,c) raw-edge sums
__device__ unsigned int g_maxbits;              // global max (float bits)

// ---- conv_in smem layout (bytes) ----
#define XSP 132                           // fp32 staging pitch (floats)
#define XS0_OFF 0                         // 32 x 132 x 4 = 16896
#define XS1_OFF 16896
#define XPITCH 136                        // bf16 X pitch
#define XH_OFF 33792                      // 32 x 136 x 2 = 8704
#define XL_OFF 42496
#define WPITCH 40                         // bf16 W pitch (32 + 8 pad)
#define WH_OFF 51200                      // 64 x 40 x 2 = 5120
#define WL_OFF 56320
#define SMEM_SZ 62208

// ---- conv_out smem layout (bytes) ----
#define O_XH 0                            // 64 x 136 x 2 = 17408
#define O_XL 17408
#define O_WPITCH 72                       // bf16 W pitch (64 + 8 pad)
#define O_WH 34816                        // 64 x 72 x 2 = 9216
#define O_WL 44032
#define O_FM 53248
#define O_PL 53504
#define O_HH 53760
#define O_SMEM 53792

// ============================ PTX helpers ==================================
__device__ __forceinline__ unsigned smem_u32(const void* p) {
    unsigned a;
    asm("{ .reg .u64 t; cvta.to.shared.u64 t, %1; cvt.u32.u64 %0, t; }" : "=r"(a) : "l"(p));
    return a;
}
__device__ __forceinline__ void cpa16(unsigned d, const void* s) {
    asm volatile("cp.async.cg.shared.global [%0], [%1], 16;" :: "r"(d), "l"(s));
}
#define CPCOMMIT() asm volatile("cp.async.commit_group;" ::: "memory")
template <int N> __device__ __forceinline__ void cpwait() {
    asm volatile("cp.async.wait_group %0;" :: "n"(N) : "memory");
}
__device__ __forceinline__ void ldsm4t(unsigned& r0, unsigned& r1, unsigned& r2,
                                       unsigned& r3, unsigned a) {
    asm volatile("ldmatrix.sync.aligned.m8n8.x4.trans.shared.b16 {%0,%1,%2,%3}, [%4];"
                 : "=r"(r0), "=r"(r1), "=r"(r2), "=r"(r3) : "r"(a));
}
__device__ __forceinline__ void ldsm4(unsigned& r0, unsigned& r1, unsigned& r2,
                                      unsigned& r3, unsigned a) {
    asm volatile("ldmatrix.sync.aligned.m8n8.x4.shared.b16 {%0,%1,%2,%3}, [%4];"
                 : "=r"(r0), "=r"(r1), "=r"(r2), "=r"(r3) : "r"(a));
}
__device__ __forceinline__ void mma16816(float* d, const unsigned* a,
                                         unsigned b0, unsigned b1) {
    asm volatile("mma.sync.aligned.m16n8k16.row.col.f32.bf16.bf16.f32 "
                 "{%0,%1,%2,%3},{%4,%5,%6,%7},{%8,%9},{%0,%1,%2,%3};"
                 : "+f"(d[0]), "+f"(d[1]), "+f"(d[2]), "+f"(d[3])
                 : "r"(a[0]), "r"(a[1]), "r"(a[2]), "r"(a[3]), "r"(b0), "r"(b1));
}
__device__ __forceinline__ unsigned pk(float a, float b) {
    __nv_bfloat162 t(__float2bfloat16(a), __float2bfloat16(b));
    return *(unsigned*)&t;
}

// ===========================================================================
// conv_in via mma.sync bf16 3-term split + cp.async pipelined staging.
// (identical math/structure to the 215.8us run; FOLD path removed)
template <int CH>
__global__ void __launch_bounds__(128, 3) k_conv(
    const float* __restrict__ src, int cin,
    const float* __restrict__ wsrc, int wrow,
    const float* __restrict__ bias, float* __restrict__ dst) {
    extern __shared__ char sm[];
    unsigned smb = smem_u32(sm);
    int tid = threadIdx.x;
    int w   = tid >> 5, lane = tid & 31;

    int t    = blockIdx.x;
    int b    = t >> 9;           // 512 tiles per batch
    int pix0 = (t & 511) << 7;   // 128 pixels per tile

    if (blockIdx.x == 0) {       // init for this replay's edge stage
        g_sums[tid] = 0.f;
        g_sums[tid + 128] = 0.f;
        if (tid == 0) g_maxbits = 0u;
    }

    const float* srcb = src + (size_t)b * cin * HW + pix0;

    auto issue_x = [&](int cs, int buf) {
        const float* base = srcb + (size_t)(cs * 32) * HW;
        unsigned db = smb + (buf ? XS1_OFF : XS0_OFF);
#pragma unroll
        for (int k = 0; k < 8; ++k) {
            int seg = tid + k * 128;               // 0..1023
            int row = seg >> 5, off = (seg & 31) * 4;
            cpa16(db + (unsigned)(row * XSP + off) * 4, base + (size_t)row * HW + off);
        }
    };

    issue_x(0, 0); CPCOMMIT();
    issue_x(1, 1); CPCOMMIT();

    float acc[2][8][4];
#pragma unroll
    for (int mt = 0; mt < 2; ++mt)
#pragma unroll
        for (int nt = 0; nt < 8; ++nt)
#pragma unroll
            for (int i = 0; i < 4; ++i) acc[mt][nt][i] = 0.f;

    int arow  = (lane & 7) + ((lane >> 4) << 3);
    int acol0 = (w << 5) + (((lane >> 3) & 1) << 3);
    int brow2 = ((lane >> 4) << 3) + (lane & 7);
    int bcol  = ((lane >> 3) & 1) << 3;

    for (int s = 0; s < CH; ++s) {
        if (s + 1 < CH) cpwait<1>(); else cpwait<0>();
        __syncthreads();

        // ---- W LDG first (L2-hot; latency hidden behind X convert below)
        int wo = tid >> 1, wc = (tid & 1) * 16;
        const float* wp = wsrc + wo * wrow + s * 32 + wc;
        float4 wa = *(const float4*)wp;
        float4 wb4 = *(const float4*)(wp + 4);
        float4 wcv = *(const float4*)(wp + 8);
        float4 wd = *(const float4*)(wp + 12);

        // ---- X convert: XS[s&1] fp32 [c][pix] -> XH/XL bf16
        {
            const char* xs = sm + ((s & 1) ? XS1_OFF : XS0_OFF);
            int cw = w * 32;
            unsigned hibuf[16], lobuf[16];
#pragma unroll
            for (int i = 0; i < 8; ++i) {
                float4 v = *(const float4*)(xs + (lane * XSP + cw + i * 4) * 4);
                float h0 = __bfloat162float(__float2bfloat16(v.x));
                float h1 = __bfloat162float(__float2bfloat16(v.y));
                float h2 = __bfloat162float(__float2bfloat16(v.z));
                float h3 = __bfloat162float(__float2bfloat16(v.w));
                hibuf[i * 2]     = pk(h0, h1);
                hibuf[i * 2 + 1] = pk(h2, h3);
                lobuf[i * 2]     = pk(v.x - h0, v.y - h1);
                lobuf[i * 2 + 1] = pk(v.z - h2, v.w - h3);
            }
            unsigned xoff = (unsigned)((lane * XPITCH + cw) * 2);
#pragma unroll
            for (int j = 0; j < 4; ++j) {
                *(uint4*)(sm + XH_OFF + xoff + j * 16) =
                    make_uint4(hibuf[j * 4], hibuf[j * 4 + 1], hibuf[j * 4 + 2], hibuf[j * 4 + 3]);
                *(uint4*)(sm + XL_OFF + xoff + j * 16) =
                    make_uint4(lobuf[j * 4], lobuf[j * 4 + 1], lobuf[j * 4 + 2], lobuf[j * 4 + 3]);
            }
        }

        // ---- W split + STS
        {
            float wv[16] = {wa.x, wa.y, wa.z, wa.w, wb4.x, wb4.y, wb4.z, wb4.w,
                            wcv.x, wcv.y, wcv.z, wcv.w, wd.x, wd.y, wd.z, wd.w};
#pragma unroll
            for (int i = 0; i < 4; ++i) {
                float h0 = __bfloat162float(__float2bfloat16(wv[i * 4]));
                float h1 = __bfloat162float(__float2bfloat16(wv[i * 4 + 1]));
                float h2 = __bfloat162float(__float2bfloat16(wv[i * 4 + 2]));
                float h3 = __bfloat162float(__float2bfloat16(wv[i * 4 + 3]));
                unsigned p0 = pk(h0, h1), p1 = pk(h2, h3);
                unsigned q0 = pk(wv[i * 4] - h0, wv[i * 4 + 1] - h1);
                unsigned q1 = pk(wv[i * 4 + 2] - h2, wv[i * 4 + 3] - h3);
                unsigned woff = (unsigned)((wo * WPITCH + wc + i * 4) * 2);
                *(uint2*)(sm + WH_OFF + woff) = make_uint2(p0, p1);
                *(uint2*)(sm + WL_OFF + woff) = make_uint2(q0, q1);
            }
        }
        __syncthreads();

        if (s + 2 < CH) { issue_x(s + 2, s & 1); CPCOMMIT(); }

        // ---- MMA: 2 k-steps of 16
#pragma unroll
        for (int ks = 0; ks < 2; ++ks) {
            unsigned ah[2][4], al[2][4];
#pragma unroll
            for (int mt = 0; mt < 2; ++mt) {
                unsigned aoff = (unsigned)(((ks * 16 + arow) * XPITCH + acol0 + mt * 16) * 2);
                ldsm4t(ah[mt][0], ah[mt][1], ah[mt][2], ah[mt][3], smb + XH_OFF + aoff);
                ldsm4t(al[mt][0], al[mt][1], al[mt][2], al[mt][3], smb + XL_OFF + aoff);
            }
#pragma unroll
            for (int ntp = 0; ntp < 4; ++ntp) {
                unsigned bh[4], bl[4];
                unsigned boff = (unsigned)(((ntp * 16 + brow2) * WPITCH + ks * 16 + bcol) * 2);
                ldsm4(bh[0], bh[1], bh[2], bh[3], smb + WH_OFF + boff);
                ldsm4(bl[0], bl[1], bl[2], bl[3], smb + WL_OFF + boff);
#pragma unroll
                for (int mt = 0; mt < 2; ++mt) {
                    mma16816(acc[mt][ntp * 2],     ah[mt], bh[0], bh[1]);
                    mma16816(acc[mt][ntp * 2],     al[mt], bh[0], bh[1]);
                    mma16816(acc[mt][ntp * 2],     ah[mt], bl[0], bl[1]);
                    mma16816(acc[mt][ntp * 2 + 1], ah[mt], bh[2], bh[3]);
                    mma16816(acc[mt][ntp * 2 + 1], al[mt], bh[2], bh[3]);
                    mma16816(acc[mt][ntp * 2 + 1], ah[mt], bl[2], bl[3]);
                }
            }
        }
    }

    // ---- epilogue
    int g  = lane >> 2;
    int t2 = (lane & 3) * 2;
#pragma unroll
    for (int mt = 0; mt < 2; ++mt) {
        float* dp = dst + (size_t)b * CMID * HW + pix0 + w * 32 + mt * 16;
#pragma unroll
        for (int nt = 0; nt < 8; ++nt) {
            int o0 = nt * 8 + t2;
            float b0 = __ldg(bias + o0), b1 = __ldg(bias + o0 + 1);
            dp[(size_t)o0 * HW + g]           = acc[mt][nt][0] + b0;
            dp[(size_t)(o0 + 1) * HW + g]     = acc[mt][nt][1] + b1;
            dp[(size_t)o0 * HW + g + 8]       = acc[mt][nt][2] + b0;
            dp[(size_t)(o0 + 1) * HW + g + 8] = acc[mt][nt][3] + b1;
        }
    }
}

// ===========================================================================
// conv_out: edge (pre-split bf16 hi/lo planes) x folded W. No staging/convert:
// cp.async lands XH/XL directly in ldsm layout; SE fold + W staging overlap
// the async loads; then 4 k-steps of MMA.
__global__ void __launch_bounds__(128, 3) k_conv_out(
    const __nv_bfloat16* __restrict__ eh, const __nv_bfloat16* __restrict__ el,
    const float* __restrict__ wsrc,
    const float* __restrict__ bias, float* __restrict__ dst,
    const float* __restrict__ w_fc1, const float* __restrict__ b_fc1,
    const float* __restrict__ w_fc2, const float* __restrict__ b_fc2) {
    extern __shared__ char sm[];
    unsigned smb = smem_u32(sm);
    int tid = threadIdx.x;
    int w   = tid >> 5, lane = tid & 31;

    int t    = blockIdx.x;
    int b    = t >> 9;
    int pix0 = (t & 511) << 7;

    // ---- cp.async ALL of X (64ch x 128px bf16 hi+lo) straight to ldsm layout
    const __nv_bfloat16* ehb = eh + (size_t)b * CMID * HW + pix0;
    const __nv_bfloat16* elb = el + (size_t)b * CMID * HW + pix0;
#pragma unroll
    for (int k = 0; k < 8; ++k) {
        int seg = tid + k * 128;                    // 0..1023
        int row = seg >> 4, off = (seg & 15) * 8;   // 16 x 16B per 128-px row
        cpa16(smb + O_XH + (unsigned)(row * XPITCH + off) * 2, ehb + (size_t)row * HW + off);
        cpa16(smb + O_XL + (unsigned)(row * XPITCH + off) * 2, elb + (size_t)row * HW + off);
    }
    CPCOMMIT();

    // ---- SE head (overlaps the async loads)
    {
        float* pooled = (float*)(sm + O_PL);
        float* hh     = (float*)(sm + O_HH);
        float* fm     = (float*)(sm + O_FM);
        float inv = 1.f / (__uint_as_float(g_maxbits) + 1e-8f);
        if (tid < 64) pooled[tid] = g_sums[b * 64 + tid] * (1.f / 65536.f) * inv;
        __syncthreads();
        if (tid < 4) {
            float s = b_fc1[tid];
            for (int cc = 0; cc < 64; ++cc) s = fmaf(w_fc1[tid * 64 + cc], pooled[cc], s);
            hh[tid] = fmaxf(s, 0.f);
        }
        __syncthreads();
        if (tid < 64) {
            float sc = b_fc2[tid];
#pragma unroll
            for (int j = 0; j < 4; ++j) sc = fmaf(w_fc2[tid * 4 + j], hh[j], sc);
            fm[tid] = inv / (1.f + expf(-sc));
        }
        __syncthreads();
    }

    // ---- W: LDG + fold + split + STS (full K=64; 32 channels per thread)
    {
        int wo = tid >> 1, wc = (tid & 1) * 32;
        const float* wp = wsrc + wo * 64 + wc;
        const float* fm = (const float*)(sm + O_FM);
        float wv[32];
#pragma unroll
        for (int i = 0; i < 8; ++i) {
            float4 v = *(const float4*)(wp + i * 4);
            wv[i * 4] = v.x; wv[i * 4 + 1] = v.y; wv[i * 4 + 2] = v.z; wv[i * 4 + 3] = v.w;
        }
#pragma unroll
        for (int i = 0; i < 32; ++i) wv[i] *= fm[wc + i];
#pragma unroll
        for (int i = 0; i < 8; ++i) {
            float h0 = __bfloat162float(__float2bfloat16(wv[i * 4]));
            float h1 = __bfloat162float(__float2bfloat16(wv[i * 4 + 1]));
            float h2 = __bfloat162float(__float2bfloat16(wv[i * 4 + 2]));
            float h3 = __bfloat162float(__float2bfloat16(wv[i * 4 + 3]));
            unsigned p0 = pk(h0, h1), p1 = pk(h2, h3);
            unsigned q0 = pk(wv[i * 4] - h0, wv[i * 4 + 1] - h1);
            unsigned q1 = pk(wv[i * 4 + 2] - h2, wv[i * 4 + 3] - h3);
            unsigned woff = (unsigned)((wo * O_WPITCH + wc + i * 4) * 2);
            *(uint2*)(sm + O_WH + woff) = make_uint2(p0, p1);
            *(uint2*)(sm + O_WL + woff) = make_uint2(q0, q1);
        }
    }
    cpwait<0>();
    __syncthreads();

    float acc[2][8][4];
#pragma unroll
    for (int mt = 0; mt < 2; ++mt)
#pragma unroll
        for (int nt = 0; nt < 8; ++nt)
#pragma unroll
            for (int i = 0; i < 4; ++i) acc[mt][nt][i] = 0.f;

    int arow  = (lane & 7) + ((lane >> 4) << 3);
    int acol0 = (w << 5) + (((lane >> 3) & 1) << 3);
    int brow2 = ((lane >> 4) << 3) + (lane & 7);
    int bcol  = ((lane >> 3) & 1) << 3;

#pragma unroll
    for (int ks = 0; ks < 4; ++ks) {
        unsigned ah[2][4], al[2][4];
#pragma unroll
        for (int mt = 0; mt < 2; ++mt) {
            unsigned aoff = (unsigned)(((ks * 16 + arow) * XPITCH + acol0 + mt * 16) * 2);
            ldsm4t(ah[mt][0], ah[mt][1], ah[mt][2], ah[mt][3], smb + O_XH + aoff);
            ldsm4t(al[mt][0], al[mt][1], al[mt][2], al[mt][3], smb + O_XL + aoff);
        }
#pragma unroll
        for (int ntp = 0; ntp < 4; ++ntp) {
            unsigned bh[4], bl[4];
            unsigned boff = (unsigned)(((ntp * 16 + brow2) * O_WPITCH + ks * 16 + bcol) * 2);
            ldsm4(bh[0], bh[1], bh[2], bh[3], smb + O_WH + boff);
            ldsm4(bl[0], bl[1], bl[2], bl[3], smb + O_WL + boff);
#pragma unroll
            for (int mt = 0; mt < 2; ++mt) {
                mma16816(acc[mt][ntp * 2],     ah[mt], bh[0], bh[1]);
                mma16816(acc[mt][ntp * 2],     al[mt], bh[0], bh[1]);
                mma16816(acc[mt][ntp * 2],     ah[mt], bl[0], bl[1]);
                mma16816(acc[mt][ntp * 2 + 1], ah[mt], bh[2], bh[3]);
                mma16816(acc[mt][ntp * 2 + 1], al[mt], bh[2], bh[3]);
                mma16816(acc[mt][ntp * 2 + 1], ah[mt], bl[2], bl[3]);
            }
        }
    }

    // ---- epilogue
    int g  = lane >> 2;
    int t2 = (lane & 3) * 2;
#pragma unroll
    for (int mt = 0; mt < 2; ++mt) {
        float* dp = dst + (size_t)b * CMID * HW + pix0 + w * 32 + mt * 16;
#pragma unroll
        for (int nt = 0; nt < 8; ++nt) {
            int o0 = nt * 8 + t2;
            float b0 = __ldg(bias + o0), b1 = __ldg(bias + o0 + 1);
            dp[(size_t)o0 * HW + g]           = acc[mt][nt][0] + b0;
            dp[(size_t)(o0 + 1) * HW + g]     = acc[mt][nt][1] + b1;
            dp[(size_t)o0 * HW + g + 8]       = acc[mt][nt][2] + b0;
            dp[(size_t)(o0 + 1) * HW + g + 8] = acc[mt][nt][3] + b1;
        }
    }
}

// ---------------------------------------------------------------------------
// Fused depthwise stage (strip layout, as in 215.8us run) — now emits
// pre-split bf16 hi/lo edge planes; reductions use exact fp32 values.
__global__ void __launch_bounds__(256) k_edge() {
    __shared__ float smraw[10240];                  // 40960 B
    float (*ys)[256] = (float(*)[256])smraw;        // 22 rows: gy = r0-3 ..
    float (*ts)[256] = (float(*)[256])(smraw + 5632); // 18 rows: gy = r0-1 ..
    float (*ss)[260] = (float(*)[260])smraw;        // 18 x 258 used, overlays ys
    __shared__ float rs[8], rm[8];

    int tid   = threadIdx.x;
    int plane = blockIdx.y;                         // b*64 + c
    int r0    = blockIdx.x * 16;
    const float* yp = g_y + (size_t)plane * HW;

    const float g1 = expf(-0.125f), g2 = expf(-0.5f);

#pragma unroll
    for (int rr = 0; rr < 22; ++rr) {
        int gy = r0 - 3 + rr;
        ys[rr][tid] = ((unsigned)gy < 256u) ? yp[gy * 256 + tid] : 0.f;
    }
    __syncthreads();

    {
        int c = tid;
        float y0 = ys[0][c], y1 = ys[1][c], y2 = ys[2][c], y3 = ys[3][c], y4 = ys[4][c];
#pragma unroll
        for (int j = 0; j < 18; ++j) {
            ts[j][c] = g2 * (y0 + y4) + g1 * (y1 + y3) + y2;
            y0 = y1; y1 = y2; y2 = y3; y3 = y4;
            if (j + 5 < 22) y4 = ys[j + 5][c];
        }
    }
    __syncthreads();

    for (int idx = tid; idx < 18 * 258; idx += 256) {
        int j = idx / 258, cc = idx - j * 258;
        int gx = cc - 1, gy = r0 - 1 + j;
        float v = 0.f;
        if ((unsigned)gy < 256u && (unsigned)gx < 256u) {
            float t0 = ((unsigned)(gx - 2) < 256u) ? ts[j][gx - 2] : 0.f;
            float t1 = ((unsigned)(gx - 1) < 256u) ? ts[j][gx - 1] : 0.f;
            float t2 = ts[j][gx];
            float t3 = ((unsigned)(gx + 1) < 256u) ? ts[j][gx + 1] : 0.f;
            float t4 = ((unsigned)(gx + 2) < 256u) ? ts[j][gx + 2] : 0.f;
            v = g2 * (t0 + t4) + g1 * (t1 + t3) + t2;
        }
        ss[j][cc] = v;
    }
    __syncthreads();

    float lsum = 0.f, lmax = 0.f;
    {
        int c = tid;
        float a0 = ss[0][c], a1 = ss[0][c + 1], a2 = ss[0][c + 2];
        float b0 = ss[1][c], b1 = ss[1][c + 1], b2 = ss[1][c + 2];
        __nv_bfloat16* eph = g_eh + (size_t)plane * HW + r0 * 256 + c;
        __nv_bfloat16* epl = g_el + (size_t)plane * HW + r0 * 256 + c;
#pragma unroll
        for (int i = 0; i < 16; ++i) {
            float c0 = ss[i + 2][c], c1 = ss[i + 2][c + 1], c2 = ss[i + 2][c + 2];
            float gx0 = 3.f * (a0 - a2) + 10.f * (b0 - b2) + 3.f * (c0 - c2);
            float gx9 = 3.f * (a0 - c0) + 10.f * (a1 - c1) + 3.f * (a2 - c2);
            float lap = 4.f * b1 - a1 - b0 - b2 - c1;
            float edge = fmaxf(fabsf(gx0), fabsf(gx9)) + 0.1f * fabsf(lap);
            __nv_bfloat16 h = __float2bfloat16(edge);
            eph[i * 256] = h;
            epl[i * 256] = __float2bfloat16(edge - __bfloat162float(h));
            lsum += edge;
            lmax = fmaxf(lmax, edge);
            a0 = b0; a1 = b1; a2 = b2;
            b0 = c0; b1 = c1; b2 = c2;
        }
    }

#pragma unroll
    for (int off = 16; off; off >>= 1) {
        lsum += __shfl_down_sync(0xffffffffu, lsum, off);
        lmax = fmaxf(lmax, __shfl_down_sync(0xffffffffu, lmax, off));
    }
    int wid = tid >> 5, lane = tid & 31;
    if (lane == 0) { rs[wid] = lsum; rm[wid] = lmax; }
    __syncthreads();
    if (tid == 0) {
        float s = 0.f, m = 0.f;
#pragma unroll
        for (int w2 = 0; w2 < 8; ++w2) { s += rs[w2]; m = fmaxf(m, rm[w2]); }
        atomicAdd(&g_sums[plane], s);
        atomicMax(&g_maxbits, __float_as_uint(m));
    }
}

// ---------------------------------------------------------------------------
extern "C" void kernel_launch(void* const* d_in, const int* in_sizes, int n_in,
                              void* d_out, int out_size) {
    const float* x     = (const float*)d_in[0];
    const float* w_in  = (const float*)d_in[1];
    const float* b_in  = (const float*)d_in[2];
    const float* w_fc1 = (const float*)d_in[3];
    const float* b_fc1 = (const float*)d_in[4];
    const float* w_fc2 = (const float*)d_in[5];
    const float* b_fc2 = (const float*)d_in[6];
    const float* w_out = (const float*)d_in[7];
    const float* b_out = (const float*)d_in[8];
    float* out = (float*)d_out;

    cudaFuncSetAttribute(k_conv<8>, cudaFuncAttributeMaxDynamicSharedMemorySize, SMEM_SZ);
    cudaFuncSetAttribute(k_conv_out, cudaFuncAttributeMaxDynamicSharedMemorySize, O_SMEM);

    float* gy = nullptr;
    __nv_bfloat16 *geh, *gel;
    cudaGetSymbolAddress((void**)&gy, g_y);
    cudaGetSymbolAddress((void**)&geh, g_eh);
    cudaGetSymbolAddress((void**)&gel, g_el);

    k_conv<8><<<2048, 128, SMEM_SZ>>>(x, 256, w_in, 256, b_in, gy);
    k_edge<<<dim3(16, 256), 256>>>();
    k_conv_out<<<2048, 128, O_SMEM>>>(geh, gel, w_out, b_out, out,
                                      w_fc1, b_fc1, w_fc2, b_fc2);
}

// round 15
// speedup vs baseline: 1.5632x; 1.1551x over previous
#include <cuda_runtime.h>
#include <cuda_bf16.h>
#include <math.h>

#define HW 65536
#define CMID 64

// ---- scratch (device globals; allocation is forbidden) ----
__device__ float g_y[4 * CMID * HW];            // after input conv1x1 (64 MiB)
__device__ __nv_bfloat16 g_eh[4 * CMID * HW];   // edge bf16 hi (32 MiB)
__device__ __nv_bfloat16 g_el[4 * CMID * HW];   // edge bf16 lo (32 MiB)
__device__ float g_sums[4 * CMID];              // per-(b,c) raw-edge sums
__device__ unsigned int g_maxbits;              // global max (float bits)

// ---- conv_in smem layout (bytes) ----
#define XPITCH 136                        // bf16 X pitch
#define XH_OFF 0                          // 32 x 136 x 2 = 8704
#define XL_OFF 8704
#define WPITCH 40                         // bf16 W pitch (32 + 8 pad)
#define WH_OFF 17408                      // 64 x 40 x 2 = 5120
#define WL_OFF 22528
#define SMEM_SZ 27648

// ---- conv_out smem layout (bytes) ----
#define O_XH 0                            // 64 x 136 x 2 = 17408
#define O_XL 17408
#define O_WPITCH 72                       // bf16 W pitch (64 + 8 pad)
#define O_WH 34816                        // 64 x 72 x 2 = 9216
#define O_WL 44032
#define O_FM 53248
#define O_PL 53504
#define O_HH 53760
#define O_SMEM 53792

// ============================ PTX helpers ==================================
__device__ __forceinline__ unsigned smem_u32(const void* p) {
    unsigned a;
    asm("{ .reg .u64 t; cvta.to.shared.u64 t, %1; cvt.u32.u64 %0, t; }" : "=r"(a) : "l"(p));
    return a;
}
__device__ __forceinline__ void cpa16(unsigned d, const void* s) {
    asm volatile("cp.async.cg.shared.global [%0], [%1], 16;" :: "r"(d), "l"(s));
}
#define CPCOMMIT() asm volatile("cp.async.commit_group;" ::: "memory")
template <int N> __device__ __forceinline__ void cpwait() {
    asm volatile("cp.async.wait_group %0;" :: "n"(N) : "memory");
}
__device__ __forceinline__ void ldsm4t(unsigned& r0, unsigned& r1, unsigned& r2,
                                       unsigned& r3, unsigned a) {
    asm volatile("ldmatrix.sync.aligned.m8n8.x4.trans.shared.b16 {%0,%1,%2,%3}, [%4];"
                 : "=r"(r0), "=r"(r1), "=r"(r2), "=r"(r3) : "r"(a));
}
__device__ __forceinline__ void ldsm4(unsigned& r0, unsigned& r1, unsigned& r2,
                                      unsigned& r3, unsigned a) {
    asm volatile("ldmatrix.sync.aligned.m8n8.x4.shared.b16 {%0,%1,%2,%3}, [%4];"
                 : "=r"(r0), "=r"(r1), "=r"(r2), "=r"(r3) : "r"(a));
}
__device__ __forceinline__ void mma16816(float* d, const unsigned* a,
                                         unsigned b0, unsigned b1) {
    asm volatile("mma.sync.aligned.m16n8k16.row.col.f32.bf16.bf16.f32 "
                 "{%0,%1,%2,%3},{%4,%5,%6,%7},{%8,%9},{%0,%1,%2,%3};"
                 : "+f"(d[0]), "+f"(d[1]), "+f"(d[2]), "+f"(d[3])
                 : "r"(a[0]), "r"(a[1]), "r"(a[2]), "r"(a[3]), "r"(b0), "r"(b1));
}
__device__ __forceinline__ unsigned pk(float a, float b) {
    __nv_bfloat162 t(__float2bfloat16(a), __float2bfloat16(b));
    return *(unsigned*)&t;
}
// pack-first bf16 hi/lo split of a float pair: bit-identical to scalar path,
// 2 fewer cvts per pair (hi floats derived from packed bits).
__device__ __forceinline__ void split2(float a, float b, unsigned& ph, unsigned& pl) {
    ph = pk(a, b);
    float h0 = __uint_as_float(ph << 16);
    float h1 = __uint_as_float(ph & 0xffff0000u);
    pl = pk(a - h0, b - h1);
}

// ===========================================================================
// conv_in via mma.sync bf16 3-term split. Register-prefetched direct LDG
// (no fp32 smem staging): warp = 8 channels x 32 lanes of 4 contiguous px;
// LDG(s+1) issued before MMA(s) so DRAM latency hides behind tensor work.
template <int CH>
__global__ void __launch_bounds__(128, 3) k_conv(
    const float* __restrict__ src, int cin,
    const float* __restrict__ wsrc, int wrow,
    const float* __restrict__ bias, float* __restrict__ dst) {
    extern __shared__ char sm[];
    unsigned smb = smem_u32(sm);
    int tid = threadIdx.x;
    int w   = tid >> 5, lane = tid & 31;

    int t    = blockIdx.x;
    int b    = t >> 9;           // 512 tiles per batch
    int pix0 = (t & 511) << 7;   // 128 pixels per tile

    if (blockIdx.x == 0) {       // init for this replay's edge stage
        g_sums[tid] = 0.f;
        g_sums[tid + 128] = 0.f;
        if (tid == 0) g_maxbits = 0u;
    }

    const float* srcb = src + (size_t)b * cin * HW + pix0;
    int cbase = w * 8;           // warp's channel offset within chunk
    int px    = lane * 4;        // this thread's 4-pixel column

    // prefetch chunk 0 into registers (coalesced: warp covers full 512B rows)
    float4 xr[8];
#pragma unroll
    for (int r = 0; r < 8; ++r)
        xr[r] = *(const float4*)(srcb + (size_t)(cbase + r) * HW + px);

    float acc[2][8][4];
#pragma unroll
    for (int mt = 0; mt < 2; ++mt)
#pragma unroll
        for (int nt = 0; nt < 8; ++nt)
#pragma unroll
            for (int i = 0; i < 4; ++i) acc[mt][nt][i] = 0.f;

    int arow  = (lane & 7) + ((lane >> 4) << 3);
    int acol0 = (w << 5) + (((lane >> 3) & 1) << 3);
    int brow2 = ((lane >> 4) << 3) + (lane & 7);
    int bcol  = ((lane >> 3) & 1) << 3;

    for (int s = 0; s < CH; ++s) {
        // ---- W LDG first (L2-hot; latency hidden behind X convert below)
        int wo = tid >> 1, wc = (tid & 1) * 16;
        const float* wp = wsrc + wo * wrow + s * 32 + wc;
        float4 wa = *(const float4*)wp;
        float4 wb4 = *(const float4*)(wp + 4);
        float4 wcv = *(const float4*)(wp + 8);
        float4 wd = *(const float4*)(wp + 12);

        // ---- X convert from registers -> XH/XL bf16 (write-through STS.64)
#pragma unroll
        for (int r = 0; r < 8; ++r) {
            float4 v = xr[r];
            unsigned h0, l0, h1, l1;
            split2(v.x, v.y, h0, l0);
            split2(v.z, v.w, h1, l1);
            unsigned off = (unsigned)(((cbase + r) * XPITCH + px) * 2);
            *(uint2*)(sm + XH_OFF + off) = make_uint2(h0, h1);
            *(uint2*)(sm + XL_OFF + off) = make_uint2(l0, l1);
        }

        // ---- W split + STS
        {
            float wv[16] = {wa.x, wa.y, wa.z, wa.w, wb4.x, wb4.y, wb4.z, wb4.w,
                            wcv.x, wcv.y, wcv.z, wcv.w, wd.x, wd.y, wd.z, wd.w};
#pragma unroll
            for (int i = 0; i < 4; ++i) {
                unsigned p0, q0, p1, q1;
                split2(wv[i * 4],     wv[i * 4 + 1], p0, q0);
                split2(wv[i * 4 + 2], wv[i * 4 + 3], p1, q1);
                unsigned woff = (unsigned)((wo * WPITCH + wc + i * 4) * 2);
                *(uint2*)(sm + WH_OFF + woff) = make_uint2(p0, p1);
                *(uint2*)(sm + WL_OFF + woff) = make_uint2(q0, q1);
            }
        }
        __syncthreads();

        // ---- issue next chunk's LDG now; latency hides behind MMA below
        if (s + 1 < CH) {
#pragma unroll
            for (int r = 0; r < 8; ++r)
                xr[r] = *(const float4*)(srcb + (size_t)((s + 1) * 32 + cbase + r) * HW + px);
        }

        // ---- MMA: 2 k-steps of 16
#pragma unroll
        for (int ks = 0; ks < 2; ++ks) {
            unsigned ah[2][4], al[2][4];
#pragma unroll
            for (int mt = 0; mt < 2; ++mt) {
                unsigned aoff = (unsigned)(((ks * 16 + arow) * XPITCH + acol0 + mt * 16) * 2);
                ldsm4t(ah[mt][0], ah[mt][1], ah[mt][2], ah[mt][3], smb + XH_OFF + aoff);
                ldsm4t(al[mt][0], al[mt][1], al[mt][2], al[mt][3], smb + XL_OFF + aoff);
            }
#pragma unroll
            for (int ntp = 0; ntp < 4; ++ntp) {
                unsigned bh[4], bl[4];
                unsigned boff = (unsigned)(((ntp * 16 + brow2) * WPITCH + ks * 16 + bcol) * 2);
                ldsm4(bh[0], bh[1], bh[2], bh[3], smb + WH_OFF + boff);
                ldsm4(bl[0], bl[1], bl[2], bl[3], smb + WL_OFF + boff);
#pragma unroll
                for (int mt = 0; mt < 2; ++mt) {
                    mma16816(acc[mt][ntp * 2],     ah[mt], bh[0], bh[1]);
                    mma16816(acc[mt][ntp * 2],     al[mt], bh[0], bh[1]);
                    mma16816(acc[mt][ntp * 2],     ah[mt], bl[0], bl[1]);
                    mma16816(acc[mt][ntp * 2 + 1], ah[mt], bh[2], bh[3]);
                    mma16816(acc[mt][ntp * 2 + 1], al[mt], bh[2], bh[3]);
                    mma16816(acc[mt][ntp * 2 + 1], ah[mt], bl[2], bl[3]);
                }
            }
        }
        __syncthreads();    // MMA reads done before next convert overwrites
    }

    // ---- epilogue
    int g  = lane >> 2;
    int t2 = (lane & 3) * 2;
#pragma unroll
    for (int mt = 0; mt < 2; ++mt) {
        float* dp = dst + (size_t)b * CMID * HW + pix0 + w * 32 + mt * 16;
#pragma unroll
        for (int nt = 0; nt < 8; ++nt) {
            int o0 = nt * 8 + t2;
            float b0 = __ldg(bias + o0), b1 = __ldg(bias + o0 + 1);
            dp[(size_t)o0 * HW + g]           = acc[mt][nt][0] + b0;
            dp[(size_t)(o0 + 1) * HW + g]     = acc[mt][nt][1] + b1;
            dp[(size_t)o0 * HW + g + 8]       = acc[mt][nt][2] + b0;
            dp[(size_t)(o0 + 1) * HW + g + 8] = acc[mt][nt][3] + b1;
        }
    }
}

// ===========================================================================
// conv_out: edge (pre-split bf16 hi/lo planes) x folded W. cp.async lands
// XH/XL directly in ldsm layout; SE fold + W staging overlap the async loads.
__global__ void __launch_bounds__(128, 3) k_conv_out(
    const __nv_bfloat16* __restrict__ eh, const __nv_bfloat16* __restrict__ el,
    const float* __restrict__ wsrc,
    const float* __restrict__ bias, float* __restrict__ dst,
    const float* __restrict__ w_fc1, const float* __restrict__ b_fc1,
    const float* __restrict__ w_fc2, const float* __restrict__ b_fc2) {
    extern __shared__ char sm[];
    unsigned smb = smem_u32(sm);
    int tid = threadIdx.x;
    int w   = tid >> 5, lane = tid & 31;

    int t    = blockIdx.x;
    int b    = t >> 9;
    int pix0 = (t & 511) << 7;

    const __nv_bfloat16* ehb = eh + (size_t)b * CMID * HW + pix0;
    const __nv_bfloat16* elb = el + (size_t)b * CMID * HW + pix0;
#pragma unroll
    for (int k = 0; k < 8; ++k) {
        int seg = tid + k * 128;                    // 0..1023
        int row = seg >> 4, off = (seg & 15) * 8;   // 16 x 16B per 128-px row
        cpa16(smb + O_XH + (unsigned)(row * XPITCH + off) * 2, ehb + (size_t)row * HW + off);
        cpa16(smb + O_XL + (unsigned)(row * XPITCH + off) * 2, elb + (size_t)row * HW + off);
    }
    CPCOMMIT();

    // ---- SE head (overlaps the async loads)
    {
        float* pooled = (float*)(sm + O_PL);
        float* hh     = (float*)(sm + O_HH);
        float* fm     = (float*)(sm + O_FM);
        float inv = 1.f / (__uint_as_float(g_maxbits) + 1e-8f);
        if (tid < 64) pooled[tid] = g_sums[b * 64 + tid] * (1.f / 65536.f) * inv;
        __syncthreads();
        if (tid < 4) {
            float s = b_fc1[tid];
            for (int cc = 0; cc < 64; ++cc) s = fmaf(w_fc1[tid * 64 + cc], pooled[cc], s);
            hh[tid] = fmaxf(s, 0.f);
        }
        __syncthreads();
        if (tid < 64) {
            float sc = b_fc2[tid];
#pragma unroll
            for (int j = 0; j < 4; ++j) sc = fmaf(w_fc2[tid * 4 + j], hh[j], sc);
            fm[tid] = inv / (1.f + expf(-sc));
        }
        __syncthreads();
    }

    // ---- W: LDG + fold + split + STS (full K=64; 32 channels per thread)
    {
        int wo = tid >> 1, wc = (tid & 1) * 32;
        const float* wp = wsrc + wo * 64 + wc;
        const float* fm = (const float*)(sm + O_FM);
        float wv[32];
#pragma unroll
        for (int i = 0; i < 8; ++i) {
            float4 v = *(const float4*)(wp + i * 4);
            wv[i * 4] = v.x; wv[i * 4 + 1] = v.y; wv[i * 4 + 2] = v.z; wv[i * 4 + 3] = v.w;
        }
#pragma unroll
        for (int i = 0; i < 32; ++i) wv[i] *= fm[wc + i];
#pragma unroll
        for (int i = 0; i < 8; ++i) {
            unsigned p0, q0, p1, q1;
            split2(wv[i * 4],     wv[i * 4 + 1], p0, q0);
            split2(wv[i * 4 + 2], wv[i * 4 + 3], p1, q1);
            unsigned woff = (unsigned)((wo * O_WPITCH + wc + i * 4) * 2);
            *(uint2*)(sm + O_WH + woff) = make_uint2(p0, p1);
            *(uint2*)(sm + O_WL + woff) = make_uint2(q0, q1);
        }
    }
    cpwait<0>();
    __syncthreads();

    float acc[2][8][4];
#pragma unroll
    for (int mt = 0; mt < 2; ++mt)
#pragma unroll
        for (int nt = 0; nt < 8; ++nt)
#pragma unroll
            for (int i = 0; i < 4; ++i) acc[mt][nt][i] = 0.f;

    int arow  = (lane & 7) + ((lane >> 4) << 3);
    int acol0 = (w << 5) + (((lane >> 3) & 1) << 3);
    int brow2 = ((lane >> 4) << 3) + (lane & 7);
    int bcol  = ((lane >> 3) & 1) << 3;

#pragma unroll
    for (int ks = 0; ks < 4; ++ks) {
        unsigned ah[2][4], al[2][4];
#pragma unroll
        for (int mt = 0; mt < 2; ++mt) {
            unsigned aoff = (unsigned)(((ks * 16 + arow) * XPITCH + acol0 + mt * 16) * 2);
            ldsm4t(ah[mt][0], ah[mt][1], ah[mt][2], ah[mt][3], smb + O_XH + aoff);
            ldsm4t(al[mt][0], al[mt][1], al[mt][2], al[mt][3], smb + O_XL + aoff);
        }
#pragma unroll
        for (int ntp = 0; ntp < 4; ++ntp) {
            unsigned bh[4], bl[4];
            unsigned boff = (unsigned)(((ntp * 16 + brow2) * O_WPITCH + ks * 16 + bcol) * 2);
            ldsm4(bh[0], bh[1], bh[2], bh[3], smb + O_WH + boff);
            ldsm4(bl[0], bl[1], bl[2], bl[3], smb + O_WL + boff);
#pragma unroll
            for (int mt = 0; mt < 2; ++mt) {
                mma16816(acc[mt][ntp * 2],     ah[mt], bh[0], bh[1]);
                mma16816(acc[mt][ntp * 2],     al[mt], bh[0], bh[1]);
                mma16816(acc[mt][ntp * 2],     ah[mt], bl[0], bl[1]);
                mma16816(acc[mt][ntp * 2 + 1], ah[mt], bh[2], bh[3]);
                mma16816(acc[mt][ntp * 2 + 1], al[mt], bh[2], bh[3]);
                mma16816(acc[mt][ntp * 2 + 1], ah[mt], bl[2], bl[3]);
            }
        }
    }

    // ---- epilogue
    int g  = lane >> 2;
    int t2 = (lane & 3) * 2;
#pragma unroll
    for (int mt = 0; mt < 2; ++mt) {
        float* dp = dst + (size_t)b * CMID * HW + pix0 + w * 32 + mt * 16;
#pragma unroll
        for (int nt = 0; nt < 8; ++nt) {
            int o0 = nt * 8 + t2;
            float b0 = __ldg(bias + o0), b1 = __ldg(bias + o0 + 1);
            dp[(size_t)o0 * HW + g]           = acc[mt][nt][0] + b0;
            dp[(size_t)(o0 + 1) * HW + g]     = acc[mt][nt][1] + b1;
            dp[(size_t)o0 * HW + g + 8]       = acc[mt][nt][2] + b0;
            dp[(size_t)(o0 + 1) * HW + g + 8] = acc[mt][nt][3] + b1;
        }
    }
}

// ---------------------------------------------------------------------------
// Fused depthwise stage (strip layout) — horizontal pass de-divisioned:
// ss cols 0 and 257 are provably zero (gx out of range), so main pass is
// exactly 256 threads x 18 rows with no integer division.
__global__ void __launch_bounds__(256) k_edge() {
    __shared__ float smraw[10240];                  // 40960 B
    float (*ys)[256] = (float(*)[256])smraw;        // 22 rows: gy = r0-3 ..
    float (*ts)[256] = (float(*)[256])(smraw + 5632); // 18 rows: gy = r0-1 ..
    float (*ss)[260] = (float(*)[260])smraw;        // 18 x 258 used, overlays ys
    __shared__ float rs[8], rm[8];

    int tid   = threadIdx.x;
    int plane = blockIdx.y;                         // b*64 + c
    int r0    = blockIdx.x * 16;
    const float* yp = g_y + (size_t)plane * HW;

    const float g1 = expf(-0.125f), g2 = expf(-0.5f);

#pragma unroll
    for (int rr = 0; rr < 22; ++rr) {
        int gy = r0 - 3 + rr;
        ys[rr][tid] = ((unsigned)gy < 256u) ? yp[gy * 256 + tid] : 0.f;
    }
    __syncthreads();

    {
        int c = tid;
        float y0 = ys[0][c], y1 = ys[1][c], y2 = ys[2][c], y3 = ys[3][c], y4 = ys[4][c];
#pragma unroll
        for (int j = 0; j < 18; ++j) {
            ts[j][c] = g2 * (y0 + y4) + g1 * (y1 + y3) + y2;
            y0 = y1; y1 = y2; y2 = y3; y3 = y4;
            if (j + 5 < 22) y4 = ys[j + 5][c];
        }
    }
    __syncthreads();

    // boundary columns (gx = -1 and gx = 256) are zero by padding
    if (tid < 18) { ss[tid][0] = 0.f; ss[tid][257] = 0.f; }
    {
        int gx = tid;                               // ss col = gx + 1
        bool m2 = (gx >= 2), m1 = (gx >= 1), p1 = (gx <= 254), p2 = (gx <= 253);
#pragma unroll
        for (int j = 0; j < 18; ++j) {
            int gy = r0 - 1 + j;
            float t0 = m2 ? ts[j][gx - 2] : 0.f;
            float t1 = m1 ? ts[j][gx - 1] : 0.f;
            float t2 = ts[j][gx];
            float t3 = p1 ? ts[j][gx + 1] : 0.f;
            float t4 = p2 ? ts[j][gx + 2] : 0.f;
            float v = g2 * (t0 + t4) + g1 * (t1 + t3) + t2;
            if ((unsigned)gy >= 256u) v = 0.f;
            ss[j][gx + 1] = v;
        }
    }
    __syncthreads();

    float lsum = 0.f, lmax = 0.f;
    {
        int c = tid;
        float a0 = ss[0][c], a1 = ss[0][c + 1], a2 = ss[0][c + 2];
        float b0 = ss[1][c], b1 = ss[1][c + 1], b2 = ss[1][c + 2];
        __nv_bfloat16* eph = g_eh + (size_t)plane * HW + r0 * 256 + c;
        __nv_bfloat16* epl = g_el + (size_t)plane * HW + r0 * 256 + c;
#pragma unroll
        for (int i = 0; i < 16; ++i) {
            float c0 = ss[i + 2][c], c1 = ss[i + 2][c + 1], c2 = ss[i + 2][c + 2];
            float gx0 = 3.f * (a0 - a2) + 10.f * (b0 - b2) + 3.f * (c0 - c2);
            float gx9 = 3.f * (a0 - c0) + 10.f * (a1 - c1) + 3.f * (a2 - c2);
            float lap = 4.f * b1 - a1 - b0 - b2 - c1;
            float edge = fmaxf(fabsf(gx0), fabsf(gx9)) + 0.1f * fabsf(lap);
            __nv_bfloat16 h = __float2bfloat16(edge);
            eph[i * 256] = h;
            epl[i * 256] = __float2bfloat16(edge - __bfloat162float(h));
            lsum += edge;
            lmax = fmaxf(lmax, edge);
            a0 = b0; a1 = b1; a2 = b2;
            b0 = c0; b1 = c1; b2 = c2;
        }
    }

#pragma unroll
    for (int off = 16; off; off >>= 1) {
        lsum += __shfl_down_sync(0xffffffffu, lsum, off);
        lmax = fmaxf(lmax, __shfl_down_sync(0xffffffffu, lmax, off));
    }
    int wid = tid >> 5, lane = tid & 31;
    if (lane == 0) { rs[wid] = lsum; rm[wid] = lmax; }
    __syncthreads();
    if (tid == 0) {
        float s = 0.f, m = 0.f;
#pragma unroll
        for (int w2 = 0; w2 < 8; ++w2) { s += rs[w2]; m = fmaxf(m, rm[w2]); }
        atomicAdd(&g_sums[plane], s);
        atomicMax(&g_maxbits, __float_as_uint(m));
    }
}

// ---------------------------------------------------------------------------
extern "C" void kernel_launch(void* const* d_in, const int* in_sizes, int n_in,
                              void* d_out, int out_size) {
    const float* x     = (const float*)d_in[0];
    const float* w_in  = (const float*)d_in[1];
    const float* b_in  = (const float*)d_in[2];
    const float* w_fc1 = (const float*)d_in[3];
    const float* b_fc1 = (const float*)d_in[4];
    const float* w_fc2 = (const float*)d_in[5];
    const float* b_fc2 = (const float*)d_in[6];
    const float* w_out = (const float*)d_in[7];
    const float* b_out = (const float*)d_in[8];
    float* out = (float*)d_out;

    cudaFuncSetAttribute(k_conv_out, cudaFuncAttributeMaxDynamicSharedMemorySize, O_SMEM);

    float* gy = nullptr;
    __nv_bfloat16 *geh, *gel;
    cudaGetSymbolAddress((void**)&gy, g_y);
    cudaGetSymbolAddress((void**)&geh, g_eh);
    cudaGetSymbolAddress((void**)&gel, g_el);

    k_conv<8><<<2048, 128, SMEM_SZ>>>(x, 256, w_in, 256, b_in, gy);
    k_edge<<<dim3(16, 256), 256>>>();
    k_conv_out<<<2048, 128, O_SMEM>>>(geh, gel, w_out, b_out, out,
                                      w_fc1, b_fc1, w_fc2, b_fc2);
}